// round 5
// baseline (speedup 1.0000x reference)
#include <cuda_runtime.h>
#include <cstdint>
#include <math.h>

#define Bn   16
#define En   1024
#define Hn   16
#define Nn   2048
#define EHn  64
#define BHn  256
#define NM1n 2047

// ---------------- scratch ----------------
__device__ float g_qstep[BHn * EHn];
__device__ float g_kstep[BHn * EHn];
__device__ float g_vstep[BHn * EHn];
__device__ float g_alr0[BHn * NM1n];
__device__ float g_alr1[BHn * NM1n];
__device__ float g_atb [BHn * NM1n];
__device__ float g_abr [BHn];
__device__ float g_atbsum_part[BHn * 4];
__device__ float g_avbot_part[BHn * 8 * EHn];
__device__ float g_attn[(size_t)Nn * Bn * En];   // A for GEMM, tf32-pre-rounded
__device__ float g_wtf[(size_t)En * En];         // W_out tf32-pre-rounded

__device__ __forceinline__ float tf32r(float f) {
    unsigned u; asm("cvt.rna.tf32.f32 %0, %1;" : "=r"(u) : "f"(f));
    return __uint_as_float(u);
}

// ---------------- kernel 0: pre-round W_out to tf32 ----------------
__global__ __launch_bounds__(256) void wround_kernel(const float* __restrict__ W) {
    int i = (blockIdx.x * 256 + threadIdx.x) * 4;
    float4 v = *(const float4*)(W + i);
    v.x = tf32r(v.x); v.y = tf32r(v.y); v.z = tf32r(v.z); v.w = tf32r(v.w);
    *(float4*)(g_wtf + i) = v;
}

// ---------------- kernel 1: qkv projections ----------------
__global__ __launch_bounds__(256) void proj_kernel(
    const float* __restrict__ query, const float* __restrict__ key,
    const float* __restrict__ value, const float* __restrict__ W,
    const float* __restrict__ bias)
{
    int w = blockIdx.x * 8 + (threadIdx.x >> 5);
    int lane = threadIdx.x & 31;
    int c = w & 1023;
    int r = (w >> 10) & 15;
    int p = w >> 14;
    const float* in = (p == 0) ? query : (p == 1) ? key : value;
    const float* wr = W + (size_t)(p * En + c) * En;
    const float* ir = in + r * En;
    float acc = 0.f;
    for (int k = lane; k < En; k += 32) acc += ir[k] * wr[k];
    #pragma unroll
    for (int o = 16; o; o >>= 1) acc += __shfl_down_sync(0xffffffffu, acc, o);
    if (lane == 0) {
        acc += bias[p * En + c];
        int h = c >> 6, e = c & 63;
        int bh = r * Hn + h;
        if (p == 0)      g_qstep[bh * EHn + e] = acc * 0.125f;
        else if (p == 1) g_kstep[bh * EHn + e] = acc;
        else             g_vstep[bh * EHn + e] = acc;
    }
}

// ---------------- kernel 2: a_tb1 + fused k_t shift-copy ----------------
__global__ __launch_bounds__(256) void atb_kernel(
    const float* __restrict__ k_t_mem, float* __restrict__ k_t_out)
{
    int bh = blockIdx.x, ck = blockIdx.y;
    int tid = threadIdx.x;
    int s0 = ck * 512;
    __shared__ float qs[EHn], ks[EHn];
    __shared__ float red[256];
    if (tid < EHn) {
        qs[tid] = g_qstep[bh * EHn + tid];
        ks[tid] = g_kstep[bh * EHn + tid];
    }
    __syncthreads();
    const float* base  = k_t_mem + (size_t)bh * EHn * Nn;
    float*       obase = k_t_out + (size_t)bh * EHn * Nn;
    float acc0 = 0.f, acc1 = 0.f;
    int sA = s0 + tid, sB = s0 + tid + 256;
    for (int e = 0; e < EHn; e++) {
        const float* row = base + (size_t)e * Nn;
        float* orow = obase + (size_t)e * Nn;
        float q = qs[e];
        float vA = row[sA], vB = row[sB];
        acc0 += q * vA; acc1 += q * vB;
        if (sA >= 1) orow[sA - 1] = vA;
        orow[sB - 1] = vB;
    }
    if (ck == 3 && tid < EHn) obase[(size_t)tid * Nn + (Nn - 1)] = ks[tid];
    float local = 0.f;
    if (sA >= 1) { float a = expf(acc0); g_atb[bh * NM1n + sA - 1] = a; local += a; }
    { float a = expf(acc1); g_atb[bh * NM1n + sB - 1] = a; local += a; }
    red[tid] = local;
    __syncthreads();
    for (int st = 128; st > 0; st >>= 1) {
        if (tid < st) red[tid] += red[tid + st];
        __syncthreads();
    }
    if (tid == 0) g_atbsum_part[bh * 4 + ck] = red[0];
    if (ck == 0) {
        __syncthreads();
        red[tid] = (tid < EHn) ? qs[tid] * ks[tid] : 0.f;
        __syncthreads();
        for (int st = 128; st > 0; st >>= 1) {
            if (tid < st) red[tid] += red[tid + st];
            __syncthreads();
        }
        if (tid == 0) g_abr[bh] = expf(red[0]);
    }
}

// ---------------- kernel 3: a_lr + fused q shift-copy ----------------
__global__ __launch_bounds__(256) void alr_kernel(
    const float* __restrict__ q_mem, const float* __restrict__ k_t_mem,
    float* __restrict__ q_out)
{
    int bh = blockIdx.x, ck = blockIdx.y;
    int tid = threadIdx.x, lane = tid & 31, warp = tid >> 5;
    __shared__ float kold[EHn], ks[EHn];
    if (tid < EHn) {
        kold[tid] = k_t_mem[(size_t)bh * EHn * Nn + (size_t)tid * Nn];
        ks[tid]   = g_kstep[bh * EHn + tid];
    }
    __syncthreads();
    const float* qbase  = q_mem + (size_t)bh * Nn * EHn;
    float*       qobase = q_out + (size_t)bh * Nn * EHn;
    int nlo = (ck == 0) ? 1 : ck * 512;
    int nhi = ck * 512 + 512;
    for (int n = nlo + warp; n < nhi; n += 8) {
        const float* row = qbase + (size_t)n * EHn;
        float q0 = row[lane], q1 = row[lane + 32];
        float* orow = qobase + (size_t)(n - 1) * EHn;
        orow[lane] = q0; orow[lane + 32] = q1;
        float d0 = q0 * kold[lane] + q1 * kold[lane + 32];
        float d1 = q0 * ks[lane]   + q1 * ks[lane + 32];
        #pragma unroll
        for (int o = 16; o; o >>= 1) {
            d0 += __shfl_down_sync(0xffffffffu, d0, o);
            d1 += __shfl_down_sync(0xffffffffu, d1, o);
        }
        if (lane == 0) {
            g_alr0[bh * NM1n + n - 1] = expf(d0);
            g_alr1[bh * NM1n + n - 1] = expf(d1);
        }
    }
    if (ck == 3 && tid < EHn)
        qobase[(size_t)(Nn - 1) * EHn + tid] = g_qstep[bh * EHn + tid];
}

// ---------------- kernel 4: av_bot partials + fused v shift-copy ----------------
__global__ __launch_bounds__(256) void avbot_kernel(
    const float* __restrict__ v_mem, float* __restrict__ v_out)
{
    int bh = blockIdx.x, ck = blockIdx.y;
    int tid = threadIdx.x;
    int e = tid & 63, ch = tid >> 6;
    int s0 = ck * 256;
    int s1 = (ck == 7) ? NM1n : s0 + 256;
    const float* vbase  = v_mem + (size_t)bh * Nn * EHn;
    float*       vobase = v_out + (size_t)bh * Nn * EHn;
    const float* atb = g_atb + bh * NM1n;
    float acc = 0.f;
    for (int s = s0 + ch; s < s1; s += 4) {
        float v = vbase[(size_t)(s + 1) * EHn + e];
        vobase[(size_t)s * EHn + e] = v;
        acc += atb[s] * v;
    }
    __shared__ float part[4][EHn];
    part[ch][e] = acc;
    __syncthreads();
    if (tid < EHn) {
        g_avbot_part[((size_t)bh * 8 + ck) * EHn + tid] =
            part[0][tid] + part[1][tid] + part[2][tid] + part[3][tid];
        if (ck == 7)
            vobase[(size_t)(Nn - 1) * EHn + tid] = g_vstep[bh * EHn + tid];
    }
}

// ---------------- kernel 5: av_top / a_sum / attn (tf32-rounded) ----------------
__global__ __launch_bounds__(256) void ew_kernel(
    const float* __restrict__ a_sum_mem, const float* __restrict__ av_mem,
    const float* __restrict__ v_mem,
    float* __restrict__ a_sum_out, float* __restrict__ av_out)
{
    int tid = threadIdx.x;
    int e = tid & 63;
    int rid = blockIdx.x * 4 + (tid >> 6);
    int bh = rid >> 11, n = rid & (Nn - 1);
    int b = bh >> 4, h = bh & 15;
    float* attn_row = g_attn + ((size_t)(n * Bn + b) * En + h * EHn);
    if (n < NM1n) {
        float al0 = g_alr0[bh * NM1n + n];
        float al1 = g_alr1[bh * NM1n + n];
        float asum = a_sum_mem[bh * NM1n + n] + al1 - al0;
        float v0 = v_mem[(size_t)bh * Nn * EHn + e];
        float vs = g_vstep[bh * EHn + e];
        float av = av_mem[((size_t)bh * NM1n + n) * EHn + e] - al0 * v0 + al1 * vs;
        attn_row[e] = tf32r(av / asum);
        if (n >= 1) {
            av_out[((size_t)bh * NM1n + (n - 1)) * EHn + e] = av;
            if (e == 0) a_sum_out[bh * NM1n + n - 1] = asum;
        }
    } else {
        float abr = g_abr[bh];
        float asum = g_atbsum_part[bh * 4] + g_atbsum_part[bh * 4 + 1]
                   + g_atbsum_part[bh * 4 + 2] + g_atbsum_part[bh * 4 + 3] + abr;
        float av = abr * g_vstep[bh * EHn + e];
        #pragma unroll
        for (int c = 0; c < 8; c++)
            av += g_avbot_part[((size_t)bh * 8 + c) * EHn + e];
        attn_row[e] = tf32r(av / asum);
        av_out[((size_t)bh * NM1n + NM1n - 1) * EHn + e] = av;
        if (e == 0) a_sum_out[bh * NM1n + NM1n - 1] = asum;
    }
}

// ---------------- kernel 6: out = attn @ W^T + bias (tf32 mma.sync, 3-stage) ------
__device__ __forceinline__ void mma_tf32(float c[4], const unsigned a[4], const unsigned b[2]) {
    asm volatile(
        "mma.sync.aligned.m16n8k8.row.col.f32.tf32.tf32.f32 "
        "{%0,%1,%2,%3},{%4,%5,%6,%7},{%8,%9},{%0,%1,%2,%3};\n"
        : "+f"(c[0]), "+f"(c[1]), "+f"(c[2]), "+f"(c[3])
        : "r"(a[0]), "r"(a[1]), "r"(a[2]), "r"(a[3]), "r"(b[0]), "r"(b[1]));
}
__device__ __forceinline__ void ldsm4(unsigned& r0, unsigned& r1, unsigned& r2, unsigned& r3,
                                      unsigned addr) {
    asm volatile("ldmatrix.sync.aligned.m8n8.x4.shared.b16 {%0,%1,%2,%3}, [%4];"
                 : "=r"(r0), "=r"(r1), "=r"(r2), "=r"(r3) : "r"(addr));
}
__device__ __forceinline__ void cpa16(unsigned dst, const float* src) {
    asm volatile("cp.async.cg.shared.global [%0], [%1], 16;" :: "r"(dst), "l"(src));
}

#define KB 16
#define LDP 20            // padded row stride in floats (80B: conflict-free for ldmatrix)
#define STAGE_BYTES 20480 // (128 A rows + 128 B rows) * LDP * 4
#define GEMM_SMEM (3 * STAGE_BYTES)

__global__ __launch_bounds__(256, 2) void gemm_kernel(
    const float* __restrict__ bias, float* __restrict__ out)
{
    extern __shared__ float smf[];
    unsigned sbase;
    asm("{ .reg .u64 t; cvta.to.shared.u64 t, %1; cvt.u32.u64 %0, t; }"
        : "=r"(sbase) : "l"(smf));
    const int K = En;
    int tid = threadIdx.x;
    int warp = tid >> 5, lane = tid & 31;
    int warp_m = warp >> 2, warp_n = warp & 3;
    int m0 = blockIdx.y * 128;
    int n0 = blockIdx.x * 128;
    const float* Ag = g_attn + (size_t)m0 * K;
    const float* Bg = g_wtf + (size_t)n0 * K;

    int lrow = tid >> 2;            // 0..63
    int lcol = (tid & 3) << 2;      // 0,4,8,12

    float c[4][4][4];
    #pragma unroll
    for (int i = 0; i < 4; i++)
        #pragma unroll
        for (int j = 0; j < 4; j++)
            #pragma unroll
            for (int k = 0; k < 4; k++) c[i][j][k] = 0.f;

    // prologue: stages 0 and 1
    #pragma unroll
    for (int t = 0; t < 2; t++) {
        int kb = t * KB;
        unsigned s = sbase + t * STAGE_BYTES;
        cpa16(s + (lrow * LDP + lcol) * 4,                Ag + (size_t)lrow * K + kb + lcol);
        cpa16(s + ((lrow + 64) * LDP + lcol) * 4,         Ag + (size_t)(lrow + 64) * K + kb + lcol);
        cpa16(s + 10240 + (lrow * LDP + lcol) * 4,        Bg + (size_t)lrow * K + kb + lcol);
        cpa16(s + 10240 + ((lrow + 64) * LDP + lcol) * 4, Bg + (size_t)(lrow + 64) * K + kb + lcol);
        asm volatile("cp.async.commit_group;");
    }

    const int T = K / KB;   // 64
    int ltile = lane >> 3, lrowin = lane & 7;
    unsigned stage_off[3] = {0u, (unsigned)STAGE_BYTES, (unsigned)(2 * STAGE_BYTES)};

    for (int t = 0; t < T; t++) {
        if (t < T - 1) { asm volatile("cp.async.wait_group 1;"); }
        else           { asm volatile("cp.async.wait_group 0;"); }
        __syncthreads();
        // issue loads for stage t+2 (buffer (t+2)%3 — readers finished at iter t-1)
        if (t + 2 < T) {
            int kb = (t + 2) * KB;
            unsigned s = sbase + stage_off[(t + 2) % 3];
            cpa16(s + (lrow * LDP + lcol) * 4,                Ag + (size_t)lrow * K + kb + lcol);
            cpa16(s + ((lrow + 64) * LDP + lcol) * 4,         Ag + (size_t)(lrow + 64) * K + kb + lcol);
            cpa16(s + 10240 + (lrow * LDP + lcol) * 4,        Bg + (size_t)lrow * K + kb + lcol);
            cpa16(s + 10240 + ((lrow + 64) * LDP + lcol) * 4, Bg + (size_t)(lrow + 64) * K + kb + lcol);
            asm volatile("cp.async.commit_group;");
        }
        unsigned sA = sbase + stage_off[t % 3];
        unsigned sB = sA + 10240;
        #pragma unroll
        for (int kk = 0; kk < KB; kk += 8) {
            unsigned a[4][4], bf[4][2];
            #pragma unroll
            for (int mf = 0; mf < 4; mf++) {
                int r = warp_m * 64 + mf * 16 + ((ltile & 1) << 3) + lrowin;
                int col = kk + ((ltile >> 1) << 2);
                ldsm4(a[mf][0], a[mf][1], a[mf][2], a[mf][3],
                      sA + (unsigned)(r * LDP + col) * 4);
            }
            #pragma unroll
            for (int np = 0; np < 2; np++) {
                int r = warp_n * 32 + np * 16 + ((ltile >> 1) << 3) + lrowin;
                int col = kk + ((ltile & 1) << 2);
                ldsm4(bf[2 * np][0], bf[2 * np][1], bf[2 * np + 1][0], bf[2 * np + 1][1],
                      sB + (unsigned)(r * LDP + col) * 4);
            }
            #pragma unroll
            for (int mf = 0; mf < 4; mf++)
                #pragma unroll
                for (int nf = 0; nf < 4; nf++)
                    mma_tf32(c[mf][nf], a[mf], bf[nf]);
        }
    }

    #pragma unroll
    for (int mf = 0; mf < 4; mf++) {
        int r = m0 + warp_m * 64 + mf * 16 + (lane >> 2);
        #pragma unroll
        for (int nf = 0; nf < 4; nf++) {
            int cc = n0 + warp_n * 32 + nf * 8 + ((lane & 3) << 1);
            float b0 = bias[cc], b1 = bias[cc + 1];
            out[(size_t)r * En + cc]           = c[mf][nf][0] + b0;
            out[(size_t)r * En + cc + 1]       = c[mf][nf][1] + b1;
            out[(size_t)(r + 8) * En + cc]     = c[mf][nf][2] + b0;
            out[(size_t)(r + 8) * En + cc + 1] = c[mf][nf][3] + b1;
        }
    }
}

// ---------------- launch ----------------
extern "C" void kernel_launch(void* const* d_in, const int* in_sizes, int n_in,
                              void* d_out, int out_size)
{
    const float* query     = (const float*)d_in[0];
    const float* key       = (const float*)d_in[1];
    const float* value     = (const float*)d_in[2];
    const float* a_sum_mem = (const float*)d_in[3];
    const float* av_mem    = (const float*)d_in[4];
    const float* q_mem     = (const float*)d_in[5];
    const float* k_t_mem   = (const float*)d_in[6];
    const float* v_mem     = (const float*)d_in[7];
    const float* ipw       = (const float*)d_in[8];
    const float* ipb       = (const float*)d_in[9];
    const float* opw       = (const float*)d_in[10];
    const float* opb       = (const float*)d_in[11];

    float* out       = (float*)d_out;
    float* a_sum_out = out + (size_t)Nn * Bn * En;
    float* av_out    = a_sum_out + (size_t)BHn * NM1n;
    float* q_out     = av_out + (size_t)BHn * NM1n * EHn;
    float* kt_out    = q_out + (size_t)BHn * Nn * EHn;
    float* v_out     = kt_out + (size_t)BHn * Nn * EHn;

    cudaFuncSetAttribute(gemm_kernel, cudaFuncAttributeMaxDynamicSharedMemorySize, GEMM_SMEM);

    wround_kernel<<<En * En / 1024, 256>>>(opw);
    proj_kernel<<<6144, 256>>>(query, key, value, ipw, ipb);
    atb_kernel<<<dim3(BHn, 4), 256>>>(k_t_mem, kt_out);
    alr_kernel<<<dim3(BHn, 4), 256>>>(q_mem, k_t_mem, q_out);
    avbot_kernel<<<dim3(BHn, 8), 256>>>(v_mem, v_out);
    ew_kernel<<<BHn * Nn / 4, 256>>>(a_sum_mem, av_mem, v_mem, a_sum_out, av_out);
    dim3 g(En / 128, (Nn * Bn) / 128);
    gemm_kernel<<<g, 256, GEMM_SMEM>>>(opb, out);
}

// round 6
// speedup vs baseline: 1.3776x; 1.3776x over previous
#include <cuda_runtime.h>
#include <cuda_fp16.h>
#include <cstdint>
#include <math.h>

#define Bn   16
#define En   1024
#define Hn   16
#define Nn   2048
#define EHn  64
#define BHn  256
#define NM1n 2047

// ---------------- scratch ----------------
__device__ float g_qstep[BHn * EHn];
__device__ float g_kstep[BHn * EHn];
__device__ float g_vstep[BHn * EHn];
__device__ float g_alr0[BHn * NM1n];
__device__ float g_alr1[BHn * NM1n];
__device__ float g_atb [BHn * NM1n];
__device__ float g_abr [BHn];
__device__ float g_atbsum_part[BHn * 4];
__device__ float g_avbot_part[BHn * 8 * EHn];
__device__ __half g_attnh[(size_t)Nn * Bn * En];  // A for GEMM (fp16)
__device__ __half g_wh[(size_t)En * En];          // W_out (fp16)

// ---------------- kernel 0: convert W_out to fp16 ----------------
__global__ __launch_bounds__(256) void whalf_kernel(const float* __restrict__ W) {
    int i = (blockIdx.x * 256 + threadIdx.x) * 8;
    float4 v0 = *(const float4*)(W + i);
    float4 v1 = *(const float4*)(W + i + 4);
    __half2 h[4];
    h[0] = __floats2half2_rn(v0.x, v0.y);
    h[1] = __floats2half2_rn(v0.z, v0.w);
    h[2] = __floats2half2_rn(v1.x, v1.y);
    h[3] = __floats2half2_rn(v1.z, v1.w);
    *(float4*)(g_wh + i) = *(float4*)h;
}

// ---------------- kernel 1: qkv projections ----------------
__global__ __launch_bounds__(256) void proj_kernel(
    const float* __restrict__ query, const float* __restrict__ key,
    const float* __restrict__ value, const float* __restrict__ W,
    const float* __restrict__ bias)
{
    int w = blockIdx.x * 8 + (threadIdx.x >> 5);
    int lane = threadIdx.x & 31;
    int c = w & 1023;
    int r = (w >> 10) & 15;
    int p = w >> 14;
    const float* in = (p == 0) ? query : (p == 1) ? key : value;
    const float* wr = W + (size_t)(p * En + c) * En;
    const float* ir = in + r * En;
    float acc = 0.f;
    for (int k = lane; k < En; k += 32) acc += ir[k] * wr[k];
    #pragma unroll
    for (int o = 16; o; o >>= 1) acc += __shfl_down_sync(0xffffffffu, acc, o);
    if (lane == 0) {
        acc += bias[p * En + c];
        int h = c >> 6, e = c & 63;
        int bh = r * Hn + h;
        if (p == 0)      g_qstep[bh * EHn + e] = acc * 0.125f;
        else if (p == 1) g_kstep[bh * EHn + e] = acc;
        else             g_vstep[bh * EHn + e] = acc;
    }
}

// ---------------- kernel 2: a_tb1 + fused k_t shift-copy ----------------
__global__ __launch_bounds__(256) void atb_kernel(
    const float* __restrict__ k_t_mem, float* __restrict__ k_t_out)
{
    int bh = blockIdx.x, ck = blockIdx.y;
    int tid = threadIdx.x;
    int s0 = ck * 512;
    __shared__ float qs[EHn], ks[EHn];
    __shared__ float red[256];
    if (tid < EHn) {
        qs[tid] = g_qstep[bh * EHn + tid];
        ks[tid] = g_kstep[bh * EHn + tid];
    }
    __syncthreads();
    const float* base  = k_t_mem + (size_t)bh * EHn * Nn;
    float*       obase = k_t_out + (size_t)bh * EHn * Nn;
    float acc0 = 0.f, acc1 = 0.f;
    int sA = s0 + tid, sB = s0 + tid + 256;
    for (int e = 0; e < EHn; e++) {
        const float* row = base + (size_t)e * Nn;
        float* orow = obase + (size_t)e * Nn;
        float q = qs[e];
        float vA = row[sA], vB = row[sB];
        acc0 += q * vA; acc1 += q * vB;
        if (sA >= 1) orow[sA - 1] = vA;
        orow[sB - 1] = vB;
    }
    if (ck == 3 && tid < EHn) obase[(size_t)tid * Nn + (Nn - 1)] = ks[tid];
    float local = 0.f;
    if (sA >= 1) { float a = expf(acc0); g_atb[bh * NM1n + sA - 1] = a; local += a; }
    { float a = expf(acc1); g_atb[bh * NM1n + sB - 1] = a; local += a; }
    red[tid] = local;
    __syncthreads();
    for (int st = 128; st > 0; st >>= 1) {
        if (tid < st) red[tid] += red[tid + st];
        __syncthreads();
    }
    if (tid == 0) g_atbsum_part[bh * 4 + ck] = red[0];
    if (ck == 0) {
        __syncthreads();
        red[tid] = (tid < EHn) ? qs[tid] * ks[tid] : 0.f;
        __syncthreads();
        for (int st = 128; st > 0; st >>= 1) {
            if (tid < st) red[tid] += red[tid + st];
            __syncthreads();
        }
        if (tid == 0) g_abr[bh] = expf(red[0]);
    }
}

// ---------------- kernel 3: a_lr + fused q shift-copy ----------------
__global__ __launch_bounds__(256) void alr_kernel(
    const float* __restrict__ q_mem, const float* __restrict__ k_t_mem,
    float* __restrict__ q_out)
{
    int bh = blockIdx.x, ck = blockIdx.y;
    int tid = threadIdx.x, lane = tid & 31, warp = tid >> 5;
    __shared__ float kold[EHn], ks[EHn];
    if (tid < EHn) {
        kold[tid] = k_t_mem[(size_t)bh * EHn * Nn + (size_t)tid * Nn];
        ks[tid]   = g_kstep[bh * EHn + tid];
    }
    __syncthreads();
    const float* qbase  = q_mem + (size_t)bh * Nn * EHn;
    float*       qobase = q_out + (size_t)bh * Nn * EHn;
    int nlo = (ck == 0) ? 1 : ck * 512;
    int nhi = ck * 512 + 512;
    for (int n = nlo + warp; n < nhi; n += 8) {
        const float* row = qbase + (size_t)n * EHn;
        float q0 = row[lane], q1 = row[lane + 32];
        float* orow = qobase + (size_t)(n - 1) * EHn;
        orow[lane] = q0; orow[lane + 32] = q1;
        float d0 = q0 * kold[lane] + q1 * kold[lane + 32];
        float d1 = q0 * ks[lane]   + q1 * ks[lane + 32];
        #pragma unroll
        for (int o = 16; o; o >>= 1) {
            d0 += __shfl_down_sync(0xffffffffu, d0, o);
            d1 += __shfl_down_sync(0xffffffffu, d1, o);
        }
        if (lane == 0) {
            g_alr0[bh * NM1n + n - 1] = expf(d0);
            g_alr1[bh * NM1n + n - 1] = expf(d1);
        }
    }
    if (ck == 3 && tid < EHn)
        qobase[(size_t)(Nn - 1) * EHn + tid] = g_qstep[bh * EHn + tid];
}

// ---------------- kernel 4: av_bot partials + fused v shift-copy ----------------
__global__ __launch_bounds__(256) void avbot_kernel(
    const float* __restrict__ v_mem, float* __restrict__ v_out)
{
    int bh = blockIdx.x, ck = blockIdx.y;
    int tid = threadIdx.x;
    int e = tid & 63, ch = tid >> 6;
    int s0 = ck * 256;
    int s1 = (ck == 7) ? NM1n : s0 + 256;
    const float* vbase  = v_mem + (size_t)bh * Nn * EHn;
    float*       vobase = v_out + (size_t)bh * Nn * EHn;
    const float* atb = g_atb + bh * NM1n;
    float acc = 0.f;
    for (int s = s0 + ch; s < s1; s += 4) {
        float v = vbase[(size_t)(s + 1) * EHn + e];
        vobase[(size_t)s * EHn + e] = v;
        acc += atb[s] * v;
    }
    __shared__ float part[4][EHn];
    part[ch][e] = acc;
    __syncthreads();
    if (tid < EHn) {
        g_avbot_part[((size_t)bh * 8 + ck) * EHn + tid] =
            part[0][tid] + part[1][tid] + part[2][tid] + part[3][tid];
        if (ck == 7)
            vobase[(size_t)(Nn - 1) * EHn + tid] = g_vstep[bh * EHn + tid];
    }
}

// ---------------- kernel 5: av_top / a_sum / attn (fp16) ----------------
__global__ __launch_bounds__(256) void ew_kernel(
    const float* __restrict__ a_sum_mem, const float* __restrict__ av_mem,
    const float* __restrict__ v_mem,
    float* __restrict__ a_sum_out, float* __restrict__ av_out)
{
    int tid = threadIdx.x;
    int e = tid & 63;
    int rid = blockIdx.x * 4 + (tid >> 6);
    int bh = rid >> 11, n = rid & (Nn - 1);
    int b = bh >> 4, h = bh & 15;
    __half* attn_row = g_attnh + ((size_t)(n * Bn + b) * En + h * EHn);
    if (n < NM1n) {
        float al0 = g_alr0[bh * NM1n + n];
        float al1 = g_alr1[bh * NM1n + n];
        float asum = a_sum_mem[bh * NM1n + n] + al1 - al0;
        float v0 = v_mem[(size_t)bh * Nn * EHn + e];
        float vs = g_vstep[bh * EHn + e];
        float av = av_mem[((size_t)bh * NM1n + n) * EHn + e] - al0 * v0 + al1 * vs;
        attn_row[e] = __float2half_rn(av / asum);
        if (n >= 1) {
            av_out[((size_t)bh * NM1n + (n - 1)) * EHn + e] = av;
            if (e == 0) a_sum_out[bh * NM1n + n - 1] = asum;
        }
    } else {
        float abr = g_abr[bh];
        float asum = g_atbsum_part[bh * 4] + g_atbsum_part[bh * 4 + 1]
                   + g_atbsum_part[bh * 4 + 2] + g_atbsum_part[bh * 4 + 3] + abr;
        float av = abr * g_vstep[bh * EHn + e];
        #pragma unroll
        for (int c = 0; c < 8; c++)
            av += g_avbot_part[((size_t)bh * 8 + c) * EHn + e];
        attn_row[e] = __float2half_rn(av / asum);
        av_out[((size_t)bh * NM1n + NM1n - 1) * EHn + e] = av;
        if (e == 0) a_sum_out[bh * NM1n + NM1n - 1] = asum;
    }
}

// ---------------- kernel 6: out = attn @ W^T + bias (fp16 mma.m16n8k16) ------
__device__ __forceinline__ void mma_f16(float c[4], const unsigned a[4], const unsigned b[2]) {
    asm volatile(
        "mma.sync.aligned.m16n8k16.row.col.f32.f16.f16.f32 "
        "{%0,%1,%2,%3},{%4,%5,%6,%7},{%8,%9},{%0,%1,%2,%3};\n"
        : "+f"(c[0]), "+f"(c[1]), "+f"(c[2]), "+f"(c[3])
        : "r"(a[0]), "r"(a[1]), "r"(a[2]), "r"(a[3]), "r"(b[0]), "r"(b[1]));
}
__device__ __forceinline__ void ldsm4(unsigned& r0, unsigned& r1, unsigned& r2, unsigned& r3,
                                      unsigned addr) {
    asm volatile("ldmatrix.sync.aligned.m8n8.x4.shared.b16 {%0,%1,%2,%3}, [%4];"
                 : "=r"(r0), "=r"(r1), "=r"(r2), "=r"(r3) : "r"(addr));
}
__device__ __forceinline__ void cpa16(unsigned dst, const void* src) {
    asm volatile("cp.async.cg.shared.global [%0], [%1], 16;" :: "r"(dst), "l"(src));
}

#define KB 32             // halves per K-tile
#define LDP 40            // padded row stride in halves (80B -> conflict-free ldmatrix)
#define ABYTES (128 * LDP * 2)     // 10240
#define STAGE_BYTES (2 * ABYTES)   // 20480
#define GEMM_SMEM (3 * STAGE_BYTES)

__global__ __launch_bounds__(256, 2) void gemm_kernel(
    const float* __restrict__ bias, float* __restrict__ out)
{
    extern __shared__ __half smh[];
    unsigned sbase;
    asm("{ .reg .u64 t; cvta.to.shared.u64 t, %1; cvt.u32.u64 %0, t; }"
        : "=r"(sbase) : "l"(smh));
    const int K = En;
    int tid = threadIdx.x;
    int warp = tid >> 5, lane = tid & 31;
    int warp_m = warp >> 2, warp_n = warp & 3;
    int m0 = blockIdx.y * 128;
    int n0 = blockIdx.x * 128;
    const __half* Ag = g_attnh + (size_t)m0 * K;
    const __half* Bg = g_wh + (size_t)n0 * K;

    int lrow = tid >> 2;            // 0..63
    int lcol = (tid & 3) << 3;      // 0,8,16,24 halves (16B chunks)

    float c[4][4][4];
    #pragma unroll
    for (int i = 0; i < 4; i++)
        #pragma unroll
        for (int j = 0; j < 4; j++)
            #pragma unroll
            for (int k = 0; k < 4; k++) c[i][j][k] = 0.f;

    // prologue: stages 0 and 1
    #pragma unroll
    for (int t = 0; t < 2; t++) {
        int kb = t * KB;
        unsigned s = sbase + t * STAGE_BYTES;
        cpa16(s + (lrow * LDP + lcol) * 2,                 Ag + (size_t)lrow * K + kb + lcol);
        cpa16(s + ((lrow + 64) * LDP + lcol) * 2,          Ag + (size_t)(lrow + 64) * K + kb + lcol);
        cpa16(s + ABYTES + (lrow * LDP + lcol) * 2,        Bg + (size_t)lrow * K + kb + lcol);
        cpa16(s + ABYTES + ((lrow + 64) * LDP + lcol) * 2, Bg + (size_t)(lrow + 64) * K + kb + lcol);
        asm volatile("cp.async.commit_group;");
    }

    const int T = K / KB;   // 32
    unsigned stage_off[3] = {0u, (unsigned)STAGE_BYTES, (unsigned)(2 * STAGE_BYTES)};

    // ldmatrix lane addressing (b16 8x8 tiles)
    int a_row  = (lane & 7) + ((lane >> 3) & 1) * 8;  // row within 16-row A tile
    int a_koff = (lane >> 4) * 8;                     // k offset within 16
    int b_nrow = lane & 7;
    int b_noff = ((lane >> 4) & 1) * 8;               // n-tile select within pair
    int b_koff = ((lane >> 3) & 1) * 8;               // k half select

    for (int t = 0; t < T; t++) {
        if (t < T - 1) { asm volatile("cp.async.wait_group 1;"); }
        else           { asm volatile("cp.async.wait_group 0;"); }
        __syncthreads();
        if (t + 2 < T) {
            int kb = (t + 2) * KB;
            unsigned s = sbase + stage_off[(t + 2) % 3];
            cpa16(s + (lrow * LDP + lcol) * 2,                 Ag + (size_t)lrow * K + kb + lcol);
            cpa16(s + ((lrow + 64) * LDP + lcol) * 2,          Ag + (size_t)(lrow + 64) * K + kb + lcol);
            cpa16(s + ABYTES + (lrow * LDP + lcol) * 2,        Bg + (size_t)lrow * K + kb + lcol);
            cpa16(s + ABYTES + ((lrow + 64) * LDP + lcol) * 2, Bg + (size_t)(lrow + 64) * K + kb + lcol);
            asm volatile("cp.async.commit_group;");
        }
        unsigned sA = sbase + stage_off[t % 3];
        unsigned sB = sA + ABYTES;
        #pragma unroll
        for (int kk = 0; kk < KB; kk += 16) {
            unsigned a[4][4], bf[4][2];
            #pragma unroll
            for (int mf = 0; mf < 4; mf++) {
                int r = warp_m * 64 + mf * 16 + a_row;
                ldsm4(a[mf][0], a[mf][1], a[mf][2], a[mf][3],
                      sA + (unsigned)(r * LDP + kk + a_koff) * 2);
            }
            #pragma unroll
            for (int pp = 0; pp < 2; pp++) {
                int bn = warp_n * 32 + pp * 16 + b_noff + b_nrow;
                ldsm4(bf[2 * pp][0], bf[2 * pp][1], bf[2 * pp + 1][0], bf[2 * pp + 1][1],
                      sB + (unsigned)(bn * LDP + kk + b_koff) * 2);
            }
            #pragma unroll
            for (int mf = 0; mf < 4; mf++)
                #pragma unroll
                for (int nf = 0; nf < 4; nf++)
                    mma_f16(c[mf][nf], a[mf], bf[nf]);
        }
    }

    #pragma unroll
    for (int mf = 0; mf < 4; mf++) {
        int r = m0 + warp_m * 64 + mf * 16 + (lane >> 2);
        #pragma unroll
        for (int nf = 0; nf < 4; nf++) {
            int cc = n0 + warp_n * 32 + nf * 8 + ((lane & 3) << 1);
            float b0 = bias[cc], b1 = bias[cc + 1];
            out[(size_t)r * En + cc]           = c[mf][nf][0] + b0;
            out[(size_t)r * En + cc + 1]       = c[mf][nf][1] + b1;
            out[(size_t)(r + 8) * En + cc]     = c[mf][nf][2] + b0;
            out[(size_t)(r + 8) * En + cc + 1] = c[mf][nf][3] + b1;
        }
    }
}

// ---------------- launch ----------------
extern "C" void kernel_launch(void* const* d_in, const int* in_sizes, int n_in,
                              void* d_out, int out_size)
{
    const float* query     = (const float*)d_in[0];
    const float* key       = (const float*)d_in[1];
    const float* value     = (const float*)d_in[2];
    const float* a_sum_mem = (const float*)d_in[3];
    const float* av_mem    = (const float*)d_in[4];
    const float* q_mem     = (const float*)d_in[5];
    const float* k_t_mem   = (const float*)d_in[6];
    const float* v_mem     = (const float*)d_in[7];
    const float* ipw       = (const float*)d_in[8];
    const float* ipb       = (const float*)d_in[9];
    const float* opw       = (const float*)d_in[10];
    const float* opb       = (const float*)d_in[11];

    float* out       = (float*)d_out;
    float* a_sum_out = out + (size_t)Nn * Bn * En;
    float* av_out    = a_sum_out + (size_t)BHn * NM1n;
    float* q_out     = av_out + (size_t)BHn * NM1n * EHn;
    float* kt_out    = q_out + (size_t)BHn * Nn * EHn;
    float* v_out     = kt_out + (size_t)BHn * Nn * EHn;

    cudaFuncSetAttribute(gemm_kernel, cudaFuncAttributeMaxDynamicSharedMemorySize, GEMM_SMEM);

    whalf_kernel<<<En * En / 2048, 256>>>(opw);
    proj_kernel<<<6144, 256>>>(query, key, value, ipw, ipb);
    atb_kernel<<<dim3(BHn, 4), 256>>>(k_t_mem, kt_out);
    alr_kernel<<<dim3(BHn, 4), 256>>>(q_mem, k_t_mem, q_out);
    avbot_kernel<<<dim3(BHn, 8), 256>>>(v_mem, v_out);
    ew_kernel<<<BHn * Nn / 4, 256>>>(a_sum_mem, av_mem, v_mem, a_sum_out, av_out);
    dim3 g(En / 128, (Nn * Bn) / 128);
    gemm_kernel<<<g, 256, GEMM_SMEM>>>(opb, out);
}

// round 7
// speedup vs baseline: 1.6206x; 1.1764x over previous
#include <cuda_runtime.h>
#include <cuda_fp16.h>
#include <cstdint>
#include <math.h>

#define Bn   16
#define En   1024
#define Hn   16
#define Nn   2048
#define EHn  64
#define BHn  256
#define NM1n 2047

// ---------------- scratch ----------------
__device__ float g_qstep[BHn * EHn];
__device__ float g_kstep[BHn * EHn];
__device__ float g_vstep[BHn * EHn];
__device__ float g_alr0[BHn * NM1n];
__device__ float g_alr1[BHn * NM1n];
__device__ float g_atb [BHn * NM1n];
__device__ float g_abr [BHn];
__device__ float g_atbsum_part[BHn * 4];
__device__ float g_avbot_part[BHn * 8 * EHn];
__device__ __half g_attnh[(size_t)Nn * Bn * En];  // A for GEMM (fp16)
__device__ __half g_wh[(size_t)En * En];          // W_out (fp16)

// ---------------- kernel 0: convert W_out to fp16 ----------------
__global__ __launch_bounds__(256) void whalf_kernel(const float* __restrict__ W) {
    int i = (blockIdx.x * 256 + threadIdx.x) * 8;
    float4 v0 = *(const float4*)(W + i);
    float4 v1 = *(const float4*)(W + i + 4);
    __half2 h[4];
    h[0] = __floats2half2_rn(v0.x, v0.y);
    h[1] = __floats2half2_rn(v0.z, v0.w);
    h[2] = __floats2half2_rn(v1.x, v1.y);
    h[3] = __floats2half2_rn(v1.z, v1.w);
    *(float4*)(g_wh + i) = *(float4*)h;
}

// ---------------- kernel 1: qkv projections ----------------
__global__ __launch_bounds__(256) void proj_kernel(
    const float* __restrict__ query, const float* __restrict__ key,
    const float* __restrict__ value, const float* __restrict__ W,
    const float* __restrict__ bias)
{
    int w = blockIdx.x * 8 + (threadIdx.x >> 5);
    int lane = threadIdx.x & 31;
    int c = w & 1023;
    int r = (w >> 10) & 15;
    int p = w >> 14;
    const float* in = (p == 0) ? query : (p == 1) ? key : value;
    const float* wr = W + (size_t)(p * En + c) * En;
    const float* ir = in + r * En;
    float acc = 0.f;
    for (int k = lane; k < En; k += 32) acc += ir[k] * wr[k];
    #pragma unroll
    for (int o = 16; o; o >>= 1) acc += __shfl_down_sync(0xffffffffu, acc, o);
    if (lane == 0) {
        acc += bias[p * En + c];
        int h = c >> 6, e = c & 63;
        int bh = r * Hn + h;
        if (p == 0)      g_qstep[bh * EHn + e] = acc * 0.125f;
        else if (p == 1) g_kstep[bh * EHn + e] = acc;
        else             g_vstep[bh * EHn + e] = acc;
    }
}

// ---------------- kernel 2: a_tb1 + fused k_t shift-copy ----------------
__global__ __launch_bounds__(256) void atb_kernel(
    const float* __restrict__ k_t_mem, float* __restrict__ k_t_out)
{
    int bh = blockIdx.x, ck = blockIdx.y;
    int tid = threadIdx.x;
    int s0 = ck * 512;
    __shared__ float qs[EHn], ks[EHn];
    __shared__ float red[256];
    if (tid < EHn) {
        qs[tid] = g_qstep[bh * EHn + tid];
        ks[tid] = g_kstep[bh * EHn + tid];
    }
    __syncthreads();
    const float* base  = k_t_mem + (size_t)bh * EHn * Nn;
    float*       obase = k_t_out + (size_t)bh * EHn * Nn;
    float acc0 = 0.f, acc1 = 0.f;
    int sA = s0 + tid, sB = s0 + tid + 256;
    for (int e = 0; e < EHn; e++) {
        const float* row = base + (size_t)e * Nn;
        float* orow = obase + (size_t)e * Nn;
        float q = qs[e];
        float vA = __ldcs(row + sA), vB = __ldcs(row + sB);
        acc0 += q * vA; acc1 += q * vB;
        if (sA >= 1) __stcs(orow + sA - 1, vA);
        __stcs(orow + sB - 1, vB);
    }
    if (ck == 3 && tid < EHn) obase[(size_t)tid * Nn + (Nn - 1)] = ks[tid];
    float local = 0.f;
    if (sA >= 1) { float a = expf(acc0); g_atb[bh * NM1n + sA - 1] = a; local += a; }
    { float a = expf(acc1); g_atb[bh * NM1n + sB - 1] = a; local += a; }
    red[tid] = local;
    __syncthreads();
    for (int st = 128; st > 0; st >>= 1) {
        if (tid < st) red[tid] += red[tid + st];
        __syncthreads();
    }
    if (tid == 0) g_atbsum_part[bh * 4 + ck] = red[0];
    if (ck == 0) {
        __syncthreads();
        red[tid] = (tid < EHn) ? qs[tid] * ks[tid] : 0.f;
        __syncthreads();
        for (int st = 128; st > 0; st >>= 1) {
            if (tid < st) red[tid] += red[tid + st];
            __syncthreads();
        }
        if (tid == 0) g_abr[bh] = expf(red[0]);
    }
}

// ---------------- kernel 3: a_lr + fused q shift-copy (vectorized) ----------------
// warp handles 4 rows/iter: lane = r*8 + sub, each lane covers 8 floats of its row
__global__ __launch_bounds__(256) void alr_kernel(
    const float* __restrict__ q_mem, const float* __restrict__ k_t_mem,
    float* __restrict__ q_out)
{
    int bh = blockIdx.x, ck = blockIdx.y;
    int tid = threadIdx.x, lane = tid & 31, warp = tid >> 5;
    __shared__ float kold[EHn], ks[EHn];
    if (tid < EHn) {
        kold[tid] = k_t_mem[(size_t)bh * EHn * Nn + (size_t)tid * Nn];
        ks[tid]   = g_kstep[bh * EHn + tid];
    }
    __syncthreads();
    int r = lane >> 3;       // row within 4-row group
    int sub = lane & 7;      // 8-float segment index
    float4 k0a = *(float4*)&kold[sub * 8];
    float4 k0b = *(float4*)&kold[sub * 8 + 4];
    float4 ksa = *(float4*)&ks[sub * 8];
    float4 ksb = *(float4*)&ks[sub * 8 + 4];
    const float* qbase  = q_mem + (size_t)bh * Nn * EHn;
    float*       qobase = q_out + (size_t)bh * Nn * EHn;
    #pragma unroll 4
    for (int it = 0; it < 16; it++) {
        int n = ck * 512 + it * 32 + warp * 4 + r;
        const float* row = qbase + (size_t)n * EHn + sub * 8;
        float4 a = __ldcs((const float4*)row);
        float4 b = __ldcs((const float4*)(row + 4));
        bool valid = (n >= 1);
        if (valid) {
            float* orow = qobase + (size_t)(n - 1) * EHn + sub * 8;
            __stcs((float4*)orow, a);
            __stcs((float4*)(orow + 4), b);
        }
        float d0 = a.x * k0a.x + a.y * k0a.y + a.z * k0a.z + a.w * k0a.w
                 + b.x * k0b.x + b.y * k0b.y + b.z * k0b.z + b.w * k0b.w;
        float d1 = a.x * ksa.x + a.y * ksa.y + a.z * ksa.z + a.w * ksa.w
                 + b.x * ksb.x + b.y * ksb.y + b.z * ksb.z + b.w * ksb.w;
        #pragma unroll
        for (int o = 4; o; o >>= 1) {
            d0 += __shfl_down_sync(0xffffffffu, d0, o, 8);
            d1 += __shfl_down_sync(0xffffffffu, d1, o, 8);
        }
        if (sub == 0 && valid) {
            g_alr0[bh * NM1n + n - 1] = expf(d0);
            g_alr1[bh * NM1n + n - 1] = expf(d1);
        }
    }
    if (ck == 3 && tid < EHn)
        qobase[(size_t)(Nn - 1) * EHn + tid] = g_qstep[bh * EHn + tid];
}

// ---------------- kernel 4: av_bot partials + fused v shift-copy (vectorized) ------
__global__ __launch_bounds__(256) void avbot_kernel(
    const float* __restrict__ v_mem, float* __restrict__ v_out)
{
    int bh = blockIdx.x, ck = blockIdx.y;        // ck in [0,8)
    int tid = threadIdx.x;
    int ex = tid & 15;        // float4 group over e
    int ch = tid >> 4;        // 16 s-chains
    int s0 = ck * 256;
    int s1 = (ck == 7) ? NM1n : s0 + 256;
    const float* vbase  = v_mem + (size_t)bh * Nn * EHn;
    float*       vobase = v_out + (size_t)bh * Nn * EHn;
    const float* atb = g_atb + bh * NM1n;
    float4 acc = make_float4(0.f, 0.f, 0.f, 0.f);
    for (int s = s0 + ch; s < s1; s += 16) {
        float4 v = __ldcs((const float4*)(vbase + (size_t)(s + 1) * EHn + ex * 4));
        __stcs((float4*)(vobase + (size_t)s * EHn + ex * 4), v);
        float a = atb[s];
        acc.x += a * v.x; acc.y += a * v.y; acc.z += a * v.z; acc.w += a * v.w;
    }
    __shared__ float part[16][EHn];
    *(float4*)&part[ch][ex * 4] = acc;
    __syncthreads();
    if (tid < 16) {
        float4 t = make_float4(0.f, 0.f, 0.f, 0.f);
        #pragma unroll
        for (int c = 0; c < 16; c++) {
            float4 p = *(float4*)&part[c][tid * 4];
            t.x += p.x; t.y += p.y; t.z += p.z; t.w += p.w;
        }
        *(float4*)(g_avbot_part + ((size_t)bh * 8 + ck) * EHn + tid * 4) = t;
        if (ck == 7) {
            float4 vs = *(float4*)(g_vstep + bh * EHn + tid * 4);
            *(float4*)(vobase + (size_t)(Nn - 1) * EHn + tid * 4) = vs;
        }
    }
}

// ---------------- kernel 5: av_top / a_sum / attn (fp16, vectorized) ----------------
__global__ __launch_bounds__(256) void ew_kernel(
    const float* __restrict__ a_sum_mem, const float* __restrict__ av_mem,
    const float* __restrict__ v_mem,
    float* __restrict__ a_sum_out, float* __restrict__ av_out)
{
    int tid = threadIdx.x;
    int ex = tid & 15;                   // float4 group over e
    int gid = tid >> 4;                  // row within block (16 rows/block)
    int rid = blockIdx.x * 16 + gid;
    int bh = rid >> 11, n = rid & (Nn - 1);
    int b = bh >> 4, h = bh & 15;
    int e4 = ex * 4;
    __half* attn_row = g_attnh + ((size_t)(n * Bn + b) * En + h * EHn) + e4;
    if (n < NM1n) {
        float al0 = 0.f, al1 = 0.f, asum = 0.f;
        if (ex == 0) {
            al0 = g_alr0[bh * NM1n + n];
            al1 = g_alr1[bh * NM1n + n];
            asum = a_sum_mem[bh * NM1n + n] + al1 - al0;
        }
        al0  = __shfl_sync(0xffffffffu, al0, 0, 16);
        al1  = __shfl_sync(0xffffffffu, al1, 0, 16);
        asum = __shfl_sync(0xffffffffu, asum, 0, 16);
        float4 v0 = *(const float4*)(v_mem + (size_t)bh * Nn * EHn + e4);
        float4 vs = *(const float4*)(g_vstep + bh * EHn + e4);
        float4 av = __ldcs((const float4*)(av_mem + ((size_t)bh * NM1n + n) * EHn + e4));
        av.x = av.x - al0 * v0.x + al1 * vs.x;
        av.y = av.y - al0 * v0.y + al1 * vs.y;
        av.z = av.z - al0 * v0.z + al1 * vs.z;
        av.w = av.w - al0 * v0.w + al1 * vs.w;
        float rs = 1.0f / asum;
        __half2 h01 = __floats2half2_rn(av.x * rs, av.y * rs);
        __half2 h23 = __floats2half2_rn(av.z * rs, av.w * rs);
        uint2 packed = make_uint2(*(unsigned*)&h01, *(unsigned*)&h23);
        *(uint2*)attn_row = packed;
        if (n >= 1) {
            __stcs((float4*)(av_out + ((size_t)bh * NM1n + (n - 1)) * EHn + e4), av);
            if (ex == 0) a_sum_out[bh * NM1n + n - 1] = asum;
        }
    } else {
        float abr = g_abr[bh];
        float asum = g_atbsum_part[bh * 4] + g_atbsum_part[bh * 4 + 1]
                   + g_atbsum_part[bh * 4 + 2] + g_atbsum_part[bh * 4 + 3] + abr;
        float4 vs = *(const float4*)(g_vstep + bh * EHn + e4);
        float4 av = make_float4(abr * vs.x, abr * vs.y, abr * vs.z, abr * vs.w);
        #pragma unroll
        for (int c = 0; c < 8; c++) {
            float4 p = *(const float4*)(g_avbot_part + ((size_t)bh * 8 + c) * EHn + e4);
            av.x += p.x; av.y += p.y; av.z += p.z; av.w += p.w;
        }
        float rs = 1.0f / asum;
        __half2 h01 = __floats2half2_rn(av.x * rs, av.y * rs);
        __half2 h23 = __floats2half2_rn(av.z * rs, av.w * rs);
        uint2 packed = make_uint2(*(unsigned*)&h01, *(unsigned*)&h23);
        *(uint2*)attn_row = packed;
        *(float4*)(av_out + ((size_t)bh * NM1n + NM1n - 1) * EHn + e4) = av;
        if (ex == 0) a_sum_out[bh * NM1n + NM1n - 1] = asum;
    }
}

// ---------------- kernel 6: out = attn @ W^T + bias (fp16 mma.m16n8k16) ------
__device__ __forceinline__ void mma_f16(float c[4], const unsigned a[4], const unsigned b[2]) {
    asm volatile(
        "mma.sync.aligned.m16n8k16.row.col.f32.f16.f16.f32 "
        "{%0,%1,%2,%3},{%4,%5,%6,%7},{%8,%9},{%0,%1,%2,%3};\n"
        : "+f"(c[0]), "+f"(c[1]), "+f"(c[2]), "+f"(c[3])
        : "r"(a[0]), "r"(a[1]), "r"(a[2]), "r"(a[3]), "r"(b[0]), "r"(b[1]));
}
__device__ __forceinline__ void ldsm4(unsigned& r0, unsigned& r1, unsigned& r2, unsigned& r3,
                                      unsigned addr) {
    asm volatile("ldmatrix.sync.aligned.m8n8.x4.shared.b16 {%0,%1,%2,%3}, [%4];"
                 : "=r"(r0), "=r"(r1), "=r"(r2), "=r"(r3) : "r"(addr));
}
__device__ __forceinline__ void cpa16(unsigned dst, const void* src) {
    asm volatile("cp.async.cg.shared.global [%0], [%1], 16;" :: "r"(dst), "l"(src));
}

#define KB 32             // halves per K-tile
#define LDP 40            // padded row stride in halves (80B -> conflict-free ldmatrix)
#define ABYTES (128 * LDP * 2)     // 10240
#define STAGE_BYTES (2 * ABYTES)   // 20480
#define GEMM_SMEM (3 * STAGE_BYTES)

__global__ __launch_bounds__(256, 2) void gemm_kernel(
    const float* __restrict__ bias, float* __restrict__ out)
{
    extern __shared__ __half smh[];
    unsigned sbase;
    asm("{ .reg .u64 t; cvta.to.shared.u64 t, %1; cvt.u32.u64 %0, t; }"
        : "=r"(sbase) : "l"(smh));
    const int K = En;
    int tid = threadIdx.x;
    int warp = tid >> 5, lane = tid & 31;
    int warp_m = warp >> 2, warp_n = warp & 3;
    int m0 = blockIdx.y * 128;
    int n0 = blockIdx.x * 128;
    const __half* Ag = g_attnh + (size_t)m0 * K;
    const __half* Bg = g_wh + (size_t)n0 * K;

    int lrow = tid >> 2;            // 0..63
    int lcol = (tid & 3) << 3;      // 0,8,16,24 halves (16B chunks)

    float c[4][4][4];
    #pragma unroll
    for (int i = 0; i < 4; i++)
        #pragma unroll
        for (int j = 0; j < 4; j++)
            #pragma unroll
            for (int k = 0; k < 4; k++) c[i][j][k] = 0.f;

    // prologue: stages 0 and 1
    #pragma unroll
    for (int t = 0; t < 2; t++) {
        int kb = t * KB;
        unsigned s = sbase + t * STAGE_BYTES;
        cpa16(s + (lrow * LDP + lcol) * 2,                 Ag + (size_t)lrow * K + kb + lcol);
        cpa16(s + ((lrow + 64) * LDP + lcol) * 2,          Ag + (size_t)(lrow + 64) * K + kb + lcol);
        cpa16(s + ABYTES + (lrow * LDP + lcol) * 2,        Bg + (size_t)lrow * K + kb + lcol);
        cpa16(s + ABYTES + ((lrow + 64) * LDP + lcol) * 2, Bg + (size_t)(lrow + 64) * K + kb + lcol);
        asm volatile("cp.async.commit_group;");
    }

    const int T = K / KB;   // 32
    unsigned stage_off[3] = {0u, (unsigned)STAGE_BYTES, (unsigned)(2 * STAGE_BYTES)};

    int a_row  = (lane & 7) + ((lane >> 3) & 1) * 8;
    int a_koff = (lane >> 4) * 8;
    int b_nrow = lane & 7;
    int b_noff = ((lane >> 4) & 1) * 8;
    int b_koff = ((lane >> 3) & 1) * 8;

    for (int t = 0; t < T; t++) {
        if (t < T - 1) { asm volatile("cp.async.wait_group 1;"); }
        else           { asm volatile("cp.async.wait_group 0;"); }
        __syncthreads();
        if (t + 2 < T) {
            int kb = (t + 2) * KB;
            unsigned s = sbase + stage_off[(t + 2) % 3];
            cpa16(s + (lrow * LDP + lcol) * 2,                 Ag + (size_t)lrow * K + kb + lcol);
            cpa16(s + ((lrow + 64) * LDP + lcol) * 2,          Ag + (size_t)(lrow + 64) * K + kb + lcol);
            cpa16(s + ABYTES + (lrow * LDP + lcol) * 2,        Bg + (size_t)lrow * K + kb + lcol);
            cpa16(s + ABYTES + ((lrow + 64) * LDP + lcol) * 2, Bg + (size_t)(lrow + 64) * K + kb + lcol);
            asm volatile("cp.async.commit_group;");
        }
        unsigned sA = sbase + stage_off[t % 3];
        unsigned sB = sA + ABYTES;
        #pragma unroll
        for (int kk = 0; kk < KB; kk += 16) {
            unsigned a[4][4], bf[4][2];
            #pragma unroll
            for (int mf = 0; mf < 4; mf++) {
                int r = warp_m * 64 + mf * 16 + a_row;
                ldsm4(a[mf][0], a[mf][1], a[mf][2], a[mf][3],
                      sA + (unsigned)(r * LDP + kk + a_koff) * 2);
            }
            #pragma unroll
            for (int pp = 0; pp < 2; pp++) {
                int bn = warp_n * 32 + pp * 16 + b_noff + b_nrow;
                ldsm4(bf[2 * pp][0], bf[2 * pp][1], bf[2 * pp + 1][0], bf[2 * pp + 1][1],
                      sB + (unsigned)(bn * LDP + kk + b_koff) * 2);
            }
            #pragma unroll
            for (int mf = 0; mf < 4; mf++)
                #pragma unroll
                for (int nf = 0; nf < 4; nf++)
                    mma_f16(c[mf][nf], a[mf], bf[nf]);
        }
    }

    #pragma unroll
    for (int mf = 0; mf < 4; mf++) {
        int r = m0 + warp_m * 64 + mf * 16 + (lane >> 2);
        #pragma unroll
        for (int nf = 0; nf < 4; nf++) {
            int cc = n0 + warp_n * 32 + nf * 8 + ((lane & 3) << 1);
            float b0 = bias[cc], b1 = bias[cc + 1];
            out[(size_t)r * En + cc]           = c[mf][nf][0] + b0;
            out[(size_t)r * En + cc + 1]       = c[mf][nf][1] + b1;
            out[(size_t)(r + 8) * En + cc]     = c[mf][nf][2] + b0;
            out[(size_t)(r + 8) * En + cc + 1] = c[mf][nf][3] + b1;
        }
    }
}

// ---------------- launch ----------------
extern "C" void kernel_launch(void* const* d_in, const int* in_sizes, int n_in,
                              void* d_out, int out_size)
{
    const float* query     = (const float*)d_in[0];
    const float* key       = (const float*)d_in[1];
    const float* value     = (const float*)d_in[2];
    const float* a_sum_mem = (const float*)d_in[3];
    const float* av_mem    = (const float*)d_in[4];
    const float* q_mem     = (const float*)d_in[5];
    const float* k_t_mem   = (const float*)d_in[6];
    const float* v_mem     = (const float*)d_in[7];
    const float* ipw       = (const float*)d_in[8];
    const float* ipb       = (const float*)d_in[9];
    const float* opw       = (const float*)d_in[10];
    const float* opb       = (const float*)d_in[11];

    float* out       = (float*)d_out;
    float* a_sum_out = out + (size_t)Nn * Bn * En;
    float* av_out    = a_sum_out + (size_t)BHn * NM1n;
    float* q_out     = av_out + (size_t)BHn * NM1n * EHn;
    float* kt_out    = q_out + (size_t)BHn * Nn * EHn;
    float* v_out     = kt_out + (size_t)BHn * Nn * EHn;

    cudaFuncSetAttribute(gemm_kernel, cudaFuncAttributeMaxDynamicSharedMemorySize, GEMM_SMEM);

    whalf_kernel<<<En * En / 2048, 256>>>(opw);
    proj_kernel<<<6144, 256>>>(query, key, value, ipw, ipb);
    atb_kernel<<<dim3(BHn, 4), 256>>>(k_t_mem, kt_out);
    alr_kernel<<<dim3(BHn, 4), 256>>>(q_mem, k_t_mem, q_out);
    avbot_kernel<<<dim3(BHn, 8), 256>>>(v_mem, v_out);
    ew_kernel<<<BHn * Nn / 16, 256>>>(a_sum_mem, av_mem, v_mem, a_sum_out, av_out);
    dim3 g(En / 128, (Nn * Bn) / 128);
    gemm_kernel<<<g, 256, GEMM_SMEM>>>(opb, out);
}